// round 1
// baseline (speedup 1.0000x reference)
#include <cuda_runtime.h>
#include <cstdint>

// Fused MHA: qkv [2048,144,384] fp32, mask [1,4,144,144] fp32 -> out [2048,144,128] fp32
// B=2048, N=144, H=4, d=32. One block per (b,h). Thread-per-query-row online softmax.
// Packed f32x2 FMA (Blackwell FFMA2, PTX-only) for 2x scalar fp32 throughput.

#define BATCH 2048
#define SEQ   144
#define HEADS 4
#define HDIM  32
#define CIN   384
#define ATTN_SCALE 0.17677669529663687f
#define NTHREADS 160

__device__ __forceinline__ void fma2(unsigned long long &acc, unsigned long long a,
                                     unsigned long long b) {
    asm("fma.rn.f32x2 %0, %1, %2, %0;" : "+l"(acc) : "l"(a), "l"(b));
}
__device__ __forceinline__ void mul2(unsigned long long &a, unsigned long long s) {
    asm("mul.rn.f32x2 %0, %0, %1;" : "+l"(a) : "l"(s));
}
__device__ __forceinline__ unsigned long long pack2(float x) {
    unsigned long long r;
    asm("mov.b64 %0, {%1, %1};" : "=l"(r) : "f"(x));
    return r;
}
__device__ __forceinline__ unsigned long long packf(float x, float y) {
    unsigned long long r;
    asm("mov.b64 %0, {%1, %2};" : "=l"(r) : "f"(x), "f"(y));
    return r;
}
__device__ __forceinline__ float2 unpack2(unsigned long long v) {
    float2 f;
    asm("mov.b64 {%0, %1}, %2;" : "=f"(f.x), "=f"(f.y) : "l"(v));
    return f;
}

__global__ __launch_bounds__(NTHREADS)
void attn_fused_kernel(const float* __restrict__ qkv,
                       const float* __restrict__ mask,
                       float* __restrict__ out) {
    // smem K/V tiles: [144 rows][8 float4] each = 18432 B each
    __shared__ float4 Ks[SEQ * 8];
    __shared__ float4 Vs[SEQ * 8];

    const int bh = blockIdx.x;
    const int b  = bh >> 2;
    const int h  = bh & 3;
    const float* base = qkv + (size_t)b * SEQ * CIN;
    const int tid = threadIdx.x;

    // Cooperative load of K and V for this (b,h) into shared memory.
    // K row j lives at base + j*384 + 128 + h*32 ; V at +256 + h*32. 16B aligned.
    for (int t = tid; t < SEQ * 8; t += NTHREADS) {
        const int row = t >> 3;
        const int c   = t & 7;
        const float* rp = base + row * CIN + 128 + h * HDIM + c * 4;
        Ks[t] = *(const float4*)(rp);
        Vs[t] = *(const float4*)(rp + 128);
    }
    __syncthreads();

    const int i = tid;  // query row
    if (i < SEQ) {
        // Load q row, pre-scaled, packed into 16 f32x2 pairs.
        unsigned long long q2[16];
        const float* qp = base + i * CIN + h * HDIM;
#pragma unroll
        for (int c = 0; c < 8; c++) {
            float4 v = *(const float4*)(qp + c * 4);
            q2[2 * c]     = packf(v.x * ATTN_SCALE, v.y * ATTN_SCALE);
            q2[2 * c + 1] = packf(v.z * ATTN_SCALE, v.w * ATTN_SCALE);
        }

        unsigned long long acc[16];
#pragma unroll
        for (int t = 0; t < 16; t++) acc[t] = 0ull;

        float mrun = -1e30f;
        float lsum = 0.0f;

        const float4* mrow =
            (const float4*)(mask + ((size_t)h * SEQ + i) * SEQ);

        for (int j0 = 0; j0 < SEQ; j0 += 4) {
            const float4 m4 = mrow[j0 >> 2];
            const float mv[4] = {m4.x, m4.y, m4.z, m4.w};
#pragma unroll
            for (int jj = 0; jj < 4; jj++) {
                const int j = j0 + jj;
                // dot(q, K[j]) via packed FMA; two accumulators for ILP
                const ulonglong2* kr = (const ulonglong2*)&Ks[j * 8];
                unsigned long long d0 = 0ull, d1 = 0ull;
#pragma unroll
                for (int c = 0; c < 8; c++) {
                    ulonglong2 kk = kr[c];     // LDS.128 (warp-uniform broadcast)
                    fma2(d0, q2[2 * c],     kk.x);
                    fma2(d1, q2[2 * c + 1], kk.y);
                }
                const float2 f0 = unpack2(d0);
                const float2 f1 = unpack2(d1);
                float s = (f0.x + f0.y) + (f1.x + f1.y) + mv[jj];

                // online softmax
                if (s > mrun) {
                    const float corr = __expf(mrun - s);  // exp(-big)=0 on first hit
                    const unsigned long long c2 = pack2(corr);
                    lsum *= corr;
#pragma unroll
                    for (int t = 0; t < 16; t++) mul2(acc[t], c2);
                    mrun = s;
                }
                const float p = __expf(s - mrun);
                lsum += p;
                const unsigned long long p2 = pack2(p);

                const ulonglong2* vr = (const ulonglong2*)&Vs[j * 8];
#pragma unroll
                for (int c = 0; c < 8; c++) {
                    ulonglong2 vv = vr[c];     // LDS.128 broadcast
                    fma2(acc[2 * c],     p2, vv.x);
                    fma2(acc[2 * c + 1], p2, vv.y);
                }
            }
        }

        const float inv = 1.0f / lsum;
        float* op = out + ((size_t)b * SEQ + i) * (HEADS * HDIM) + h * HDIM;
#pragma unroll
        for (int c = 0; c < 8; c++) {
            const float2 a0 = unpack2(acc[2 * c]);
            const float2 a1 = unpack2(acc[2 * c + 1]);
            float4 o;
            o.x = a0.x * inv;
            o.y = a0.y * inv;
            o.z = a1.x * inv;
            o.w = a1.y * inv;
            *(float4*)(op + c * 4) = o;
        }
    }
}

extern "C" void kernel_launch(void* const* d_in, const int* in_sizes, int n_in,
                              void* d_out, int out_size) {
    const float* qkv  = (const float*)d_in[0];
    const float* mask = (const float*)d_in[1];
    float* out = (float*)d_out;
    attn_fused_kernel<<<BATCH * HEADS, NTHREADS>>>(qkv, mask, out);
}

// round 5
// speedup vs baseline: 3.0318x; 3.0318x over previous
#include <cuda_runtime.h>
#include <cstdint>

// Fused MHA via tf32 warp-MMA flash attention.
// qkv [2048,144,384] fp32, mask [1,4,144,144] fp32 -> out [2048,144,128] fp32
// One CTA per (b,h): 9 warps, each owns one 16-row query tile.
// QK^T and PV on mma.sync.m16n8k8.tf32; mask folded into MMA C-operand;
// QK D-fragment reused as PV A-fragment via V row permutation (no shuffles).
// K/V in static smem (36KB); Q loaded per-warp straight from global.

#define BATCH 2048
#define SEQ   144
#define HEADS 4
#define HDIM  32
#define CIN   384
#define ATTN_SCALE 0.17677669529663687f
#define LOG2E 1.4426950408889634f
#define NTHREADS 288

__device__ __forceinline__ unsigned cvt_tf32(float x) {
    unsigned r;
    asm("cvt.rna.tf32.f32 %0, %1;" : "=r"(r) : "f"(x));
    return r;
}
__device__ __forceinline__ float ex2(float x) {
    float r;
    asm("ex2.approx.ftz.f32 %0, %1;" : "=f"(r) : "f"(x));
    return r;
}
__device__ __forceinline__ void mma_tf32(float& d0, float& d1, float& d2, float& d3,
                                         unsigned a0, unsigned a1, unsigned a2, unsigned a3,
                                         unsigned b0, unsigned b1) {
    asm("mma.sync.aligned.m16n8k8.row.col.f32.tf32.tf32.f32 "
        "{%0,%1,%2,%3}, {%4,%5,%6,%7}, {%8,%9}, {%0,%1,%2,%3};"
        : "+f"(d0), "+f"(d1), "+f"(d2), "+f"(d3)
        : "r"(a0), "r"(a1), "r"(a2), "r"(a3), "r"(b0), "r"(b1));
}

__global__ __launch_bounds__(NTHREADS, 2)
void attn_mma_kernel(const float* __restrict__ qkv,
                     const float* __restrict__ mask,
                     float* __restrict__ out) {
    // K: [144][32] tf32, swizzle k ^ ((row&7)<<2)
    // V: rows permuted within 8-row groups, swizzle n ^ ((p&3)<<3)
    __shared__ unsigned Ksm[SEQ * HDIM];
    __shared__ unsigned Vsm[SEQ * HDIM];

    const int bh = blockIdx.x;
    const int b  = bh >> 2;
    const int h  = bh & 3;
    const float* base = qkv + (size_t)b * SEQ * CIN;
    const int tid = threadIdx.x;

    // ---- stage K, V into smem as tf32 (RNA-rounded) ----
    for (int t = tid; t < SEQ * 8; t += NTHREADS) {
        const int row = t >> 3;
        const int c4  = (t & 7) << 2;
        const float* rp = base + row * CIN + 128 + h * HDIM + c4;
        const float4 kv = *(const float4*)(rp);
        const float4 vv = *(const float4*)(rp + 128);

        uint4 kk;
        kk.x = cvt_tf32(kv.x); kk.y = cvt_tf32(kv.y);
        kk.z = cvt_tf32(kv.z); kk.w = cvt_tf32(kv.w);
        *(uint4*)&Ksm[row * 32 + (c4 ^ ((row & 7) << 2))] = kk;

        // V row permutation within 8-row groups: p = base | (j>>1)&3 | (j&1)<<2
        const int p = (row & ~7) | ((row >> 1) & 3) | ((row & 1) << 2);
        uint4 vvq;
        vvq.x = cvt_tf32(vv.x); vvq.y = cvt_tf32(vv.y);
        vvq.z = cvt_tf32(vv.z); vvq.w = cvt_tf32(vv.w);
        *(uint4*)&Vsm[p * 32 + (c4 ^ ((p & 3) << 3))] = vvq;
    }

    const int warp = tid >> 5;
    const int lane = tid & 31;
    const int g = lane >> 2;   // group id (row within tile / col j within chunk)
    const int c = lane & 3;    // thread-in-group
    const int i0 = warp * 16;  // query tile base row

    // ---- Q A-fragments straight from global (each element read once) ----
    unsigned qf[16];
    {
        const float* q0 = base + (i0 + g) * CIN + h * HDIM;
        const float* q1 = q0 + 8 * CIN;
#pragma unroll
        for (int kc = 0; kc < 4; kc++) {
            const int k0 = kc * 8 + c;
            qf[kc * 4 + 0] = cvt_tf32(__ldg(q0 + k0)     * ATTN_SCALE);
            qf[kc * 4 + 1] = cvt_tf32(__ldg(q1 + k0)     * ATTN_SCALE);
            qf[kc * 4 + 2] = cvt_tf32(__ldg(q0 + k0 + 4) * ATTN_SCALE);
            qf[kc * 4 + 3] = cvt_tf32(__ldg(q1 + k0 + 4) * ATTN_SCALE);
        }
    }

    float o[16];
#pragma unroll
    for (int e = 0; e < 16; e++) o[e] = 0.0f;
    float mL_lo = -1e30f, mL_hi = -1e30f;  // running max, log2 domain
    float l_lo = 0.0f, l_hi = 0.0f;        // running denom

    const float* mrow_lo = mask + (size_t)(h * SEQ + i0 + g) * SEQ;
    const float* mrow_hi = mrow_lo + 8 * SEQ;

    __syncthreads();

#pragma unroll
    for (int half = 0; half < 2; half++) {
        const int jb = half * 72;
        float s[36];

        // init accumulators with mask (C operand of QK mma)
#pragma unroll
        for (int nt = 0; nt < 9; nt++) {
            const int col = jb + nt * 8 + 2 * c;
            const float2 mlo = *(const float2*)(mrow_lo + col);
            const float2 mhi = *(const float2*)(mrow_hi + col);
            s[nt * 4 + 0] = mlo.x; s[nt * 4 + 1] = mlo.y;
            s[nt * 4 + 2] = mhi.x; s[nt * 4 + 3] = mhi.y;
        }

        // S = Q K^T + mask
#pragma unroll
        for (int nt = 0; nt < 9; nt++) {
            const int jr = jb + nt * 8 + g;
            const int sw = (jr & 7) << 2;
            const unsigned* krow = &Ksm[jr * 32];
#pragma unroll
            for (int kc = 0; kc < 4; kc++) {
                const unsigned b0 = krow[(kc * 8 + c)     ^ sw];
                const unsigned b1 = krow[(kc * 8 + c + 4) ^ sw];
                mma_tf32(s[nt * 4], s[nt * 4 + 1], s[nt * 4 + 2], s[nt * 4 + 3],
                         qf[kc * 4], qf[kc * 4 + 1], qf[kc * 4 + 2], qf[kc * 4 + 3],
                         b0, b1);
            }
        }

        // online softmax (base-2)
        float mx_lo = -1e30f, mx_hi = -1e30f;
#pragma unroll
        for (int nt = 0; nt < 9; nt++) {
            mx_lo = fmaxf(mx_lo, fmaxf(s[nt * 4 + 0], s[nt * 4 + 1]));
            mx_hi = fmaxf(mx_hi, fmaxf(s[nt * 4 + 2], s[nt * 4 + 3]));
        }
        mx_lo = fmaxf(mx_lo, __shfl_xor_sync(0xffffffffu, mx_lo, 1));
        mx_lo = fmaxf(mx_lo, __shfl_xor_sync(0xffffffffu, mx_lo, 2));
        mx_hi = fmaxf(mx_hi, __shfl_xor_sync(0xffffffffu, mx_hi, 1));
        mx_hi = fmaxf(mx_hi, __shfl_xor_sync(0xffffffffu, mx_hi, 2));

        const float nm_lo = fmaxf(mL_lo, mx_lo * LOG2E);
        const float nm_hi = fmaxf(mL_hi, mx_hi * LOG2E);
        const float corr_lo = ex2(mL_lo - nm_lo);
        const float corr_hi = ex2(mL_hi - nm_hi);
        mL_lo = nm_lo; mL_hi = nm_hi;
        l_lo *= corr_lo; l_hi *= corr_hi;
#pragma unroll
        for (int e = 0; e < 16; e++) o[e] *= (e & 2) ? corr_hi : corr_lo;

        float sl = 0.0f, sh = 0.0f;
#pragma unroll
        for (int nt = 0; nt < 9; nt++) {
            const float p0 = ex2(fmaf(s[nt * 4 + 0], LOG2E, -mL_lo));
            const float p1 = ex2(fmaf(s[nt * 4 + 1], LOG2E, -mL_lo));
            const float p2 = ex2(fmaf(s[nt * 4 + 2], LOG2E, -mL_hi));
            const float p3 = ex2(fmaf(s[nt * 4 + 3], LOG2E, -mL_hi));
            sl += p0 + p1; sh += p2 + p3;
            s[nt * 4 + 0] = __uint_as_float(cvt_tf32(p0));
            s[nt * 4 + 1] = __uint_as_float(cvt_tf32(p1));
            s[nt * 4 + 2] = __uint_as_float(cvt_tf32(p2));
            s[nt * 4 + 3] = __uint_as_float(cvt_tf32(p3));
        }
        sl += __shfl_xor_sync(0xffffffffu, sl, 1);
        sl += __shfl_xor_sync(0xffffffffu, sl, 2);
        sh += __shfl_xor_sync(0xffffffffu, sh, 1);
        sh += __shfl_xor_sync(0xffffffffu, sh, 2);
        l_lo += sl; l_hi += sh;

        // O += P V  (D-frag of S reused directly as A-frag; V rows pre-permuted)
#pragma unroll
        for (int kc = 0; kc < 9; kc++) {
            const int p0r = jb + kc * 8 + c;
            const int p1r = p0r + 4;
            const unsigned* v0 = &Vsm[p0r * 32];
            const unsigned* v1 = &Vsm[p1r * 32];
            const int sw0 = (p0r & 3) << 3;
            const int sw1 = (p1r & 3) << 3;
            const unsigned a0 = __float_as_uint(s[kc * 4 + 0]);
            const unsigned a1 = __float_as_uint(s[kc * 4 + 2]);
            const unsigned a2 = __float_as_uint(s[kc * 4 + 1]);
            const unsigned a3 = __float_as_uint(s[kc * 4 + 3]);
#pragma unroll
            for (int on = 0; on < 4; on++) {
                const unsigned b0 = v0[(on * 8 + g) ^ sw0];
                const unsigned b1 = v1[(on * 8 + g) ^ sw1];
                mma_tf32(o[on * 4], o[on * 4 + 1], o[on * 4 + 2], o[on * 4 + 3],
                         a0, a1, a2, a3, b0, b1);
            }
        }
    }

    // ---- normalize and store ----
    const float il = 1.0f / l_lo;
    const float ih = 1.0f / l_hi;
    float* ob = out + ((size_t)b * SEQ + i0 + g) * (HEADS * HDIM) + h * HDIM;
#pragma unroll
    for (int on = 0; on < 4; on++) {
        *(float2*)(ob + on * 8 + 2 * c) =
            make_float2(o[on * 4 + 0] * il, o[on * 4 + 1] * il);
        *(float2*)(ob + 8 * (HEADS * HDIM) + on * 8 + 2 * c) =
            make_float2(o[on * 4 + 2] * ih, o[on * 4 + 3] * ih);
    }
}

extern "C" void kernel_launch(void* const* d_in, const int* in_sizes, int n_in,
                              void* d_out, int out_size) {
    const float* qkv  = (const float*)d_in[0];
    const float* mask = (const float*)d_in[1];
    float* out = (float*)d_out;
    attn_mma_kernel<<<BATCH * HEADS, NTHREADS>>>(qkv, mask, out);
}

// round 6
// speedup vs baseline: 3.3127x; 1.0927x over previous
#include <cuda_runtime.h>
#include <cstdint>

// Fused MHA via tf32 warp-MMA flash attention (round 6).
// qkv [2048,144,384] fp32, mask [1,4,144,144] fp32 -> out [2048,144,128] fp32
// One CTA per (b,h): 9 warps x 16-row query tiles; 48-column chunks (s[24]);
// 3 CTAs/SM; K and V stored in paired layouts so every MMA b-fragment pair is
// a single conflict-free LDS.64. Mask folded into MMA C-operand; QK D-fragment
// reused as PV A-fragment (slot permutation baked into V layout).

#define BATCH 2048
#define SEQ   144
#define HEADS 4
#define HDIM  32
#define CIN   384
#define ATTN_SCALE 0.17677669529663687f
#define LOG2E 1.4426950408889634f
#define NTHREADS 288

__device__ __forceinline__ unsigned cvt_tf32(float x) {
    unsigned r;
    asm("cvt.rna.tf32.f32 %0, %1;" : "=r"(r) : "f"(x));
    return r;
}
__device__ __forceinline__ float ex2(float x) {
    float r;
    asm("ex2.approx.ftz.f32 %0, %1;" : "=f"(r) : "f"(x));
    return r;
}
__device__ __forceinline__ void mma_tf32(float& d0, float& d1, float& d2, float& d3,
                                         unsigned a0, unsigned a1, unsigned a2, unsigned a3,
                                         unsigned b0, unsigned b1) {
    asm("mma.sync.aligned.m16n8k8.row.col.f32.tf32.tf32.f32 "
        "{%0,%1,%2,%3}, {%4,%5,%6,%7}, {%8,%9}, {%0,%1,%2,%3};"
        : "+f"(d0), "+f"(d1), "+f"(d2), "+f"(d3)
        : "r"(a0), "r"(a1), "r"(a2), "r"(a3), "r"(b0), "r"(b1));
}

__global__ __launch_bounds__(NTHREADS, 3)
void attn_mma_kernel(const float* __restrict__ qkv,
                     const float* __restrict__ mask,
                     float* __restrict__ out) {
    // K: row*32 + ((kc*8 + pos(u)) ^ ((row&3)<<3)), pos(u) = ((u&3)<<1)|(u>>2)
    //    -> b-frag pair (k=kc*8+c, +4) adjacent => LDS.64, conflict-free.
    // V: (arow>>3)*256 + ((arow>>1)&3)*64 + ((2n + (arow&1)) ^ (((arow>>1)&3)<<3))
    //    -> PV b-frag pair (slot c: actual row 2c; slot c+4: 2c+1) adjacent => LDS.64.
    __shared__ unsigned Ksm[SEQ * HDIM];
    __shared__ unsigned Vsm[SEQ * HDIM];

    const int bh = blockIdx.x;
    const int b  = bh >> 2;
    const int h  = bh & 3;
    const float* base = qkv + (size_t)b * SEQ * CIN;
    const int tid = threadIdx.x;

    // ---- stage K, V into smem as tf32 (RNA-rounded), paired layouts ----
    for (int t = tid; t < SEQ * 8; t += NTHREADS) {
        const int row = t >> 3;
        const int c4  = (t & 7) << 2;
        const float* rp = base + row * CIN + 128 + h * HDIM + c4;
        const float4 kv = *(const float4*)(rp);
        const float4 vv = *(const float4*)(rp + 128);

        // K: k = c4+kk -> kc = c4>>3, pos = 2*kk + ((c4>>2)&1)
        const int kc = c4 >> 3;
        const int eK = (c4 >> 2) & 1;
        const int ksw = (row & 3) << 3;
        unsigned* krow = &Ksm[row * 32];
        krow[(kc * 8 + 0 + eK) ^ ksw] = cvt_tf32(kv.x);
        krow[(kc * 8 + 2 + eK) ^ ksw] = cvt_tf32(kv.y);
        krow[(kc * 8 + 4 + eK) ^ ksw] = cvt_tf32(kv.z);
        krow[(kc * 8 + 6 + eK) ^ ksw] = cvt_tf32(kv.w);

        // V: n = c4+kk
        const int eV  = row & 1;
        const int cc  = (row >> 1) & 3;
        const int vsw = cc << 3;
        unsigned* vblk = &Vsm[(row >> 3) * 256 + cc * 64];
        vblk[(2 * (c4 + 0) + eV) ^ vsw] = cvt_tf32(vv.x);
        vblk[(2 * (c4 + 1) + eV) ^ vsw] = cvt_tf32(vv.y);
        vblk[(2 * (c4 + 2) + eV) ^ vsw] = cvt_tf32(vv.z);
        vblk[(2 * (c4 + 3) + eV) ^ vsw] = cvt_tf32(vv.w);
    }

    const int warp = tid >> 5;
    const int lane = tid & 31;
    const int g = lane >> 2;   // row within tile / col within 8-group
    const int c = lane & 3;    // thread-in-group
    const int i0 = warp * 16;  // query tile base row

    // ---- Q A-fragments straight from global (each element read once) ----
    unsigned qf[16];
    {
        const float* q0 = base + (i0 + g) * CIN + h * HDIM;
        const float* q1 = q0 + 8 * CIN;
#pragma unroll
        for (int kc = 0; kc < 4; kc++) {
            const int k0 = kc * 8 + c;
            qf[kc * 4 + 0] = cvt_tf32(__ldg(q0 + k0)     * ATTN_SCALE);
            qf[kc * 4 + 1] = cvt_tf32(__ldg(q1 + k0)     * ATTN_SCALE);
            qf[kc * 4 + 2] = cvt_tf32(__ldg(q0 + k0 + 4) * ATTN_SCALE);
            qf[kc * 4 + 3] = cvt_tf32(__ldg(q1 + k0 + 4) * ATTN_SCALE);
        }
    }

    float o[16];
#pragma unroll
    for (int e = 0; e < 16; e++) o[e] = 0.0f;
    float mL_lo = -1e30f, mL_hi = -1e30f;  // running max, log2 domain
    float l_lo = 0.0f, l_hi = 0.0f;        // running denom

    const float* mrow_lo = mask + (size_t)(h * SEQ + i0 + g) * SEQ;
    const float* mrow_hi = mrow_lo + 8 * SEQ;

    __syncthreads();

#pragma unroll
    for (int chunk = 0; chunk < 3; chunk++) {
        const int jb = chunk * 48;
        float s[24];

        // init accumulators with mask (C operand of QK mma)
#pragma unroll
        for (int nt = 0; nt < 6; nt++) {
            const int col = jb + nt * 8 + 2 * c;
            const float2 mlo = *(const float2*)(mrow_lo + col);
            const float2 mhi = *(const float2*)(mrow_hi + col);
            s[nt * 4 + 0] = mlo.x; s[nt * 4 + 1] = mlo.y;
            s[nt * 4 + 2] = mhi.x; s[nt * 4 + 3] = mhi.y;
        }

        // S = Q K^T + mask   (b-frag pair = one LDS.64)
#pragma unroll
        for (int nt = 0; nt < 6; nt++) {
            const int jr = jb + nt * 8 + g;
            const int sw = (g & 3) << 3;
            const unsigned* krow = &Ksm[jr * 32];
#pragma unroll
            for (int kc = 0; kc < 4; kc++) {
                const uint2 bb = *(const uint2*)&krow[(kc * 8 + 2 * c) ^ sw];
                mma_tf32(s[nt * 4], s[nt * 4 + 1], s[nt * 4 + 2], s[nt * 4 + 3],
                         qf[kc * 4], qf[kc * 4 + 1], qf[kc * 4 + 2], qf[kc * 4 + 3],
                         bb.x, bb.y);
            }
        }

        // online softmax (base-2)
        float mx_lo = -1e30f, mx_hi = -1e30f;
#pragma unroll
        for (int nt = 0; nt < 6; nt++) {
            mx_lo = fmaxf(mx_lo, fmaxf(s[nt * 4 + 0], s[nt * 4 + 1]));
            mx_hi = fmaxf(mx_hi, fmaxf(s[nt * 4 + 2], s[nt * 4 + 3]));
        }
        mx_lo = fmaxf(mx_lo, __shfl_xor_sync(0xffffffffu, mx_lo, 1));
        mx_lo = fmaxf(mx_lo, __shfl_xor_sync(0xffffffffu, mx_lo, 2));
        mx_hi = fmaxf(mx_hi, __shfl_xor_sync(0xffffffffu, mx_hi, 1));
        mx_hi = fmaxf(mx_hi, __shfl_xor_sync(0xffffffffu, mx_hi, 2));

        const float nm_lo = fmaxf(mL_lo, mx_lo * LOG2E);
        const float nm_hi = fmaxf(mL_hi, mx_hi * LOG2E);
        const float corr_lo = ex2(mL_lo - nm_lo);
        const float corr_hi = ex2(mL_hi - nm_hi);
        mL_lo = nm_lo; mL_hi = nm_hi;
        l_lo *= corr_lo; l_hi *= corr_hi;
#pragma unroll
        for (int e = 0; e < 16; e++) o[e] *= (e & 2) ? corr_hi : corr_lo;

        float sl = 0.0f, sh = 0.0f;
#pragma unroll
        for (int nt = 0; nt < 6; nt++) {
            const float p0 = ex2(fmaf(s[nt * 4 + 0], LOG2E, -mL_lo));
            const float p1 = ex2(fmaf(s[nt * 4 + 1], LOG2E, -mL_lo));
            const float p2 = ex2(fmaf(s[nt * 4 + 2], LOG2E, -mL_hi));
            const float p3 = ex2(fmaf(s[nt * 4 + 3], LOG2E, -mL_hi));
            sl += p0 + p1; sh += p2 + p3;
            s[nt * 4 + 0] = __uint_as_float(cvt_tf32(p0));
            s[nt * 4 + 1] = __uint_as_float(cvt_tf32(p1));
            s[nt * 4 + 2] = __uint_as_float(cvt_tf32(p2));
            s[nt * 4 + 3] = __uint_as_float(cvt_tf32(p3));
        }
        sl += __shfl_xor_sync(0xffffffffu, sl, 1);
        sl += __shfl_xor_sync(0xffffffffu, sl, 2);
        sh += __shfl_xor_sync(0xffffffffu, sh, 1);
        sh += __shfl_xor_sync(0xffffffffu, sh, 2);
        l_lo += sl; l_hi += sh;

        // O += P V  (D-frag reused as A-frag; V pair layout -> one LDS.64)
#pragma unroll
        for (int kc = 0; kc < 6; kc++) {
            const int grp = chunk * 6 + kc;
            const unsigned* vblk = &Vsm[grp * 256 + c * 64];
            const int sw = c << 3;
            const unsigned a0 = __float_as_uint(s[kc * 4 + 0]);
            const unsigned a1 = __float_as_uint(s[kc * 4 + 2]);
            const unsigned a2 = __float_as_uint(s[kc * 4 + 1]);
            const unsigned a3 = __float_as_uint(s[kc * 4 + 3]);
#pragma unroll
            for (int on = 0; on < 4; on++) {
                const uint2 bb = *(const uint2*)&vblk[(on * 16 + g * 2) ^ sw];
                mma_tf32(o[on * 4], o[on * 4 + 1], o[on * 4 + 2], o[on * 4 + 3],
                         a0, a1, a2, a3, bb.x, bb.y);
            }
        }
    }

    // ---- normalize and store ----
    const float il = 1.0f / l_lo;
    const float ih = 1.0f / l_hi;
    float* ob = out + ((size_t)b * SEQ + i0 + g) * (HEADS * HDIM) + h * HDIM;
#pragma unroll
    for (int on = 0; on < 4; on++) {
        *(float2*)(ob + on * 8 + 2 * c) =
            make_float2(o[on * 4 + 0] * il, o[on * 4 + 1] * il);
        *(float2*)(ob + 8 * (HEADS * HDIM) + on * 8 + 2 * c) =
            make_float2(o[on * 4 + 2] * ih, o[on * 4 + 3] * ih);
    }
}

extern "C" void kernel_launch(void* const* d_in, const int* in_sizes, int n_in,
                              void* d_out, int out_size) {
    const float* qkv  = (const float*)d_in[0];
    const float* mask = (const float*)d_in[1];
    float* out = (float*)d_out;
    attn_mma_kernel<<<BATCH * HEADS, NTHREADS>>>(qkv, mask, out);
}

// round 16
// speedup vs baseline: 3.3587x; 1.0139x over previous
#include <cuda_runtime.h>
#include <cstdint>

// Fused MHA via tf32 warp-MMA flash attention (round 7).
// qkv [2048,144,384] fp32, mask [1,4,144,144] fp32 -> out [2048,144,128] fp32
// One CTA per (b,h): 9 warps x 16-row query tiles; 48-col chunks; 3 CTAs/SM.
// L1-wavefront optimizations:
//  - Column-block permutation: MMA block ntg (q=ntg>>1, par=ntg&1) owns columns
//    j(n) = 16q + 4*(n>>1) + 2*par + (n&1). Mask C-init for a block pair is one
//    contiguous float4 per row (no shuffles). K rows / V groups permuted to match.
//  - Q staged through smem (Vsm reused as scratch) with coalesced float4 LDGs.
//  - All fragment smem reads are conflict-free LDS.64 pairs.

#define BATCH 2048
#define SEQ   144
#define HEADS 4
#define HDIM  32
#define CIN   384
#define ATTN_SCALE 0.17677669529663687f
#define LOG2E 1.4426950408889634f
#define NTHREADS 288

__device__ __forceinline__ unsigned cvt_tf32(float x) {
    unsigned r;
    asm("cvt.rna.tf32.f32 %0, %1;" : "=r"(r) : "f"(x));
    return r;
}
__device__ __forceinline__ float ex2(float x) {
    float r;
    asm("ex2.approx.ftz.f32 %0, %1;" : "=f"(r) : "f"(x));
    return r;
}
__device__ __forceinline__ void mma_tf32(float& d0, float& d1, float& d2, float& d3,
                                         unsigned a0, unsigned a1, unsigned a2, unsigned a3,
                                         unsigned b0, unsigned b1) {
    asm("mma.sync.aligned.m16n8k8.row.col.f32.tf32.tf32.f32 "
        "{%0,%1,%2,%3}, {%4,%5,%6,%7}, {%8,%9}, {%0,%1,%2,%3};"
        : "+f"(d0), "+f"(d1), "+f"(d2), "+f"(d3)
        : "r"(a0), "r"(a1), "r"(a2), "r"(a3), "r"(b0), "r"(b1));
}

__global__ __launch_bounds__(NTHREADS, 3)
void attn_mma_kernel(const float* __restrict__ qkv,
                     const float* __restrict__ mask,
                     float* __restrict__ out) {
    // K: row*32 + ((kc*8 + 2*(k&3) + ((k>>2)&1)) ^ sw(row)),
    //    sw(row) = ((row&1)<<3)|((row&4)<<2)  (per-thread read sw = (g&3)<<3).
    // V: grp(r)=((r>>4)<<1)|((r>>1)&1); cc=(r>>2)&3; e=r&1;
    //    idx = grp*256 + cc*64 + ((2*ncol + e) ^ (cc<<3)).
    __shared__ unsigned Ksm[SEQ * HDIM];
    __shared__ unsigned Vsm[SEQ * HDIM];

    const int bh = blockIdx.x;
    const int b  = bh >> 2;
    const int h  = bh & 3;
    const float* base = qkv + (size_t)b * SEQ * CIN;
    const int tid = threadIdx.x;

    // ---- Phase A: stage Q (into Vsm scratch, swizzle (row&3)<<3) and K ----
    for (int t = tid; t < SEQ * 8; t += NTHREADS) {
        const int row = t >> 3;
        const int c4  = (t & 7) << 2;
        const int kc  = c4 >> 3;
        const int e   = (c4 >> 2) & 1;
        const float* rp = base + row * CIN + h * HDIM + c4;

        const float4 qv = *(const float4*)(rp);
        const int qsw = (row & 3) << 3;
        unsigned* qrow = &Vsm[row * 32];
        qrow[(kc * 8 + 0 + e) ^ qsw] = cvt_tf32(qv.x * ATTN_SCALE);
        qrow[(kc * 8 + 2 + e) ^ qsw] = cvt_tf32(qv.y * ATTN_SCALE);
        qrow[(kc * 8 + 4 + e) ^ qsw] = cvt_tf32(qv.z * ATTN_SCALE);
        qrow[(kc * 8 + 6 + e) ^ qsw] = cvt_tf32(qv.w * ATTN_SCALE);

        const float4 kv = *(const float4*)(rp + 128);
        const int ksw = ((row & 1) << 3) | ((row & 4) << 2);
        unsigned* krow = &Ksm[row * 32];
        krow[(kc * 8 + 0 + e) ^ ksw] = cvt_tf32(kv.x);
        krow[(kc * 8 + 2 + e) ^ ksw] = cvt_tf32(kv.y);
        krow[(kc * 8 + 4 + e) ^ ksw] = cvt_tf32(kv.z);
        krow[(kc * 8 + 6 + e) ^ ksw] = cvt_tf32(kv.w);
    }
    __syncthreads();

    const int warp = tid >> 5;
    const int lane = tid & 31;
    const int g = lane >> 2;   // row within tile / col-slot within block
    const int c = lane & 3;    // thread-in-group
    const int i0 = warp * 16;  // query tile base row
    const int sw = (g & 3) << 3;

    // ---- Q A-fragments from smem (conflict-free LDS.64 pairs) ----
    unsigned qf[16];
    {
        const unsigned* q0 = &Vsm[(i0 + g) * 32];
        const unsigned* q1 = &Vsm[(i0 + g + 8) * 32];
#pragma unroll
        for (int kc = 0; kc < 4; kc++) {
            const uint2 a = *(const uint2*)&q0[(kc * 8 + 2 * c) ^ sw];
            const uint2 d = *(const uint2*)&q1[(kc * 8 + 2 * c) ^ sw];
            qf[kc * 4 + 0] = a.x;
            qf[kc * 4 + 1] = d.x;
            qf[kc * 4 + 2] = a.y;
            qf[kc * 4 + 3] = d.y;
        }
    }
    __syncthreads();

    // ---- Phase B: stage V into Vsm (permuted groups) ----
    for (int t = tid; t < SEQ * 8; t += NTHREADS) {
        const int row = t >> 3;
        const int c4  = (t & 7) << 2;
        const float4 vv = *(const float4*)(base + row * CIN + 256 + h * HDIM + c4);

        const int grp = ((row >> 4) << 1) | ((row >> 1) & 1);
        const int cc  = (row >> 2) & 3;
        const int ev  = row & 1;
        const int vsw = cc << 3;
        unsigned* vblk = &Vsm[grp * 256 + cc * 64];
        vblk[(2 * (c4 + 0) + ev) ^ vsw] = cvt_tf32(vv.x);
        vblk[(2 * (c4 + 1) + ev) ^ vsw] = cvt_tf32(vv.y);
        vblk[(2 * (c4 + 2) + ev) ^ vsw] = cvt_tf32(vv.z);
        vblk[(2 * (c4 + 3) + ev) ^ vsw] = cvt_tf32(vv.w);
    }

    float o[16];
#pragma unroll
    for (int e = 0; e < 16; e++) o[e] = 0.0f;
    float mL_lo = -1e30f, mL_hi = -1e30f;  // running max, log2 domain
    float l_lo = 0.0f, l_hi = 0.0f;        // running denom

    const float* mbase = mask + (size_t)(h * SEQ + i0 + g) * SEQ;

    __syncthreads();

#pragma unroll
    for (int chunk = 0; chunk < 3; chunk++) {
        float s[24];

        // ---- mask C-init: one float4 per (row, q-group) covers a block pair ----
#pragma unroll
        for (int ql = 0; ql < 3; ql++) {
            const int coff = chunk * 48 + ql * 16 + 4 * c;
            const float4 flo = __ldg((const float4*)(mbase + coff));
            const float4 fhi = __ldg((const float4*)(mbase + 8 * SEQ + coff));
            s[(2 * ql) * 4 + 0] = flo.x; s[(2 * ql) * 4 + 1] = flo.y;
            s[(2 * ql) * 4 + 2] = fhi.x; s[(2 * ql) * 4 + 3] = fhi.y;
            s[(2 * ql + 1) * 4 + 0] = flo.z; s[(2 * ql + 1) * 4 + 1] = flo.w;
            s[(2 * ql + 1) * 4 + 2] = fhi.z; s[(2 * ql + 1) * 4 + 3] = fhi.w;
        }

        // ---- S = Q K^T + mask (permuted K rows; b-frag pair = one LDS.64) ----
#pragma unroll
        for (int nt = 0; nt < 6; nt++) {
            const int ntg = chunk * 6 + nt;
            const int jr = ((ntg >> 1) << 4) + ((g >> 1) << 2) + ((ntg & 1) << 1) + (g & 1);
            const unsigned* krow = &Ksm[jr * 32];
#pragma unroll
            for (int kc = 0; kc < 4; kc++) {
                const uint2 bb = *(const uint2*)&krow[(kc * 8 + 2 * c) ^ sw];
                mma_tf32(s[nt * 4], s[nt * 4 + 1], s[nt * 4 + 2], s[nt * 4 + 3],
                         qf[kc * 4], qf[kc * 4 + 1], qf[kc * 4 + 2], qf[kc * 4 + 3],
                         bb.x, bb.y);
            }
        }

        // ---- online softmax (base-2) ----
        float mx_lo = -1e30f, mx_hi = -1e30f;
#pragma unroll
        for (int nt = 0; nt < 6; nt++) {
            mx_lo = fmaxf(mx_lo, fmaxf(s[nt * 4 + 0], s[nt * 4 + 1]));
            mx_hi = fmaxf(mx_hi, fmaxf(s[nt * 4 + 2], s[nt * 4 + 3]));
        }
        mx_lo = fmaxf(mx_lo, __shfl_xor_sync(0xffffffffu, mx_lo, 1));
        mx_lo = fmaxf(mx_lo, __shfl_xor_sync(0xffffffffu, mx_lo, 2));
        mx_hi = fmaxf(mx_hi, __shfl_xor_sync(0xffffffffu, mx_hi, 1));
        mx_hi = fmaxf(mx_hi, __shfl_xor_sync(0xffffffffu, mx_hi, 2));

        const float nm_lo = fmaxf(mL_lo, mx_lo * LOG2E);
        const float nm_hi = fmaxf(mL_hi, mx_hi * LOG2E);
        const float corr_lo = ex2(mL_lo - nm_lo);
        const float corr_hi = ex2(mL_hi - nm_hi);
        mL_lo = nm_lo; mL_hi = nm_hi;
        l_lo *= corr_lo; l_hi *= corr_hi;
#pragma unroll
        for (int e = 0; e < 16; e++) o[e] *= (e & 2) ? corr_hi : corr_lo;

        float sl = 0.0f, sh = 0.0f;
#pragma unroll
        for (int nt = 0; nt < 6; nt++) {
            const float p0 = ex2(fmaf(s[nt * 4 + 0], LOG2E, -mL_lo));
            const float p1 = ex2(fmaf(s[nt * 4 + 1], LOG2E, -mL_lo));
            const float p2 = ex2(fmaf(s[nt * 4 + 2], LOG2E, -mL_hi));
            const float p3 = ex2(fmaf(s[nt * 4 + 3], LOG2E, -mL_hi));
            sl += p0 + p1; sh += p2 + p3;
            s[nt * 4 + 0] = __uint_as_float(cvt_tf32(p0));
            s[nt * 4 + 1] = __uint_as_float(cvt_tf32(p1));
            s[nt * 4 + 2] = __uint_as_float(cvt_tf32(p2));
            s[nt * 4 + 3] = __uint_as_float(cvt_tf32(p3));
        }
        sl += __shfl_xor_sync(0xffffffffu, sl, 1);
        sl += __shfl_xor_sync(0xffffffffu, sl, 2);
        sh += __shfl_xor_sync(0xffffffffu, sh, 1);
        sh += __shfl_xor_sync(0xffffffffu, sh, 2);
        l_lo += sl; l_hi += sh;

        // ---- O += P V (D-frag reused as A-frag; V pair = one LDS.64) ----
#pragma unroll
        for (int kc = 0; kc < 6; kc++) {
            const int grp = chunk * 6 + kc;
            const unsigned* vblk = &Vsm[grp * 256 + c * 64];
            const int swv = c << 3;
            const unsigned a0 = __float_as_uint(s[kc * 4 + 0]);
            const unsigned a1 = __float_as_uint(s[kc * 4 + 2]);
            const unsigned a2 = __float_as_uint(s[kc * 4 + 1]);
            const unsigned a3 = __float_as_uint(s[kc * 4 + 3]);
#pragma unroll
            for (int on = 0; on < 4; on++) {
                const uint2 bb = *(const uint2*)&vblk[(on * 16 + 2 * g) ^ swv];
                mma_tf32(o[on * 4], o[on * 4 + 1], o[on * 4 + 2], o[on * 4 + 3],
                         a0, a1, a2, a3, bb.x, bb.y);
            }
        }
    }

    // ---- normalize and store ----
    const float il = 1.0f / l_lo;
    const float ih = 1.0f / l_hi;
    float* ob = out + ((size_t)b * SEQ + i0 + g) * (HEADS * HDIM) + h * HDIM;
#pragma unroll
    for (int on = 0; on < 4; on++) {
        *(float2*)(ob + on * 8 + 2 * c) =
            make_float2(o[on * 4 + 0] * il, o[on * 4 + 1] * il);
        *(float2*)(ob + 8 * (HEADS * HDIM) + on * 8 + 2 * c) =
            make_float2(o[on * 4 + 2] * ih, o[on * 4 + 3] * ih);
    }
}

extern "C" void kernel_launch(void* const* d_in, const int* in_sizes, int n_in,
                              void* d_out, int out_size) {
    const float* qkv  = (const float*)d_in[0];
    const float* mask = (const float*)d_in[1];
    float* out = (float*)d_out;
    attn_mma_kernel<<<BATCH * HEADS, NTHREADS>>>(qkv, mask, out);
}